// round 2
// baseline (speedup 1.0000x reference)
#include <cuda_runtime.h>

#define NUM_K 512
#define DIM 64
#define HW 4096
#define CHW 262144        // 64 * 4096
#define NPOS 131072       // 32 * 64 * 64
#define QELEMS 8388608    // 32 * 64 * 64 * 64  (= NPOS * DIM)
#define TILE 256
// smem: weights 32768 f32 + wnorm 512 f32 + hist 512 u32
#define SMEM_BYTES ((32768 + 512) * 4 + 512 * 4)

__device__ double g_loss;
__device__ unsigned int g_counts[NUM_K];
__device__ float g_wnorm[NUM_K];

__global__ void vq_init(const float* __restrict__ w) {
    int k = threadIdx.x;
    const float* wr = w + k * DIM;
    float s = 0.f;
#pragma unroll
    for (int d = 0; d < DIM; d++) s += wr[d] * wr[d];
    g_wnorm[k] = s;
    g_counts[k] = 0u;
    if (k == 0) g_loss = 0.0;
}

__global__ __launch_bounds__(TILE) void vq_main(const float* __restrict__ x,
                                                const float* __restrict__ w,
                                                float* __restrict__ out) {
    extern __shared__ float smem[];
    float* ws = smem;                                     // 32768 floats (codebook)
    float* wn = smem + 32768;                             // 512 floats (||w||^2)
    unsigned int* hist = (unsigned int*)(smem + 33280);   // 512 u32

    const int tid = threadIdx.x;

    // Stage codebook into smem (coalesced float4)
    const float4* wsrc = (const float4*)w;
    float4* wdst = (float4*)ws;
#pragma unroll 8
    for (int i = tid; i < 8192; i += TILE) wdst[i] = wsrc[i];
    for (int i = tid; i < NUM_K; i += TILE) { wn[i] = g_wnorm[i]; hist[i] = 0u; }
    __syncthreads();

    const int p  = blockIdx.x * TILE + tid;   // flattened NHW position
    const int n  = p >> 12;
    const int hw = p & 4095;
    const float* xb = x + n * CHW + hw;

    // Load this position's 64-dim vector (coalesced across threads), pack into f32x2 regs
    unsigned long long xr[32];
    float xnorm = 0.f;
#pragma unroll
    for (int j = 0; j < 32; j++) {
        float a = xb[(2 * j) * HW];
        float b = xb[(2 * j + 1) * HW];
        xnorm += a * a;
        xnorm += b * b;
        asm("mov.b64 %0, {%1, %2};" : "=l"(xr[j]) : "f"(a), "f"(b));
    }

    float bestd = 3.402823466e38f;
    int bestk = 0;

#pragma unroll 2
    for (int k = 0; k < NUM_K; k++) {
        const ulonglong2* wp = (const ulonglong2*)(ws + k * DIM);
        unsigned long long a0 = 0ull, a1 = 0ull, a2 = 0ull, a3 = 0ull;
#pragma unroll
        for (int j = 0; j < 8; j++) {
            ulonglong2 w0 = wp[2 * j];
            ulonglong2 w1 = wp[2 * j + 1];
            asm("fma.rn.f32x2 %0, %1, %2, %0;" : "+l"(a0) : "l"(xr[4 * j + 0]), "l"(w0.x));
            asm("fma.rn.f32x2 %0, %1, %2, %0;" : "+l"(a1) : "l"(xr[4 * j + 1]), "l"(w0.y));
            asm("fma.rn.f32x2 %0, %1, %2, %0;" : "+l"(a2) : "l"(xr[4 * j + 2]), "l"(w1.x));
            asm("fma.rn.f32x2 %0, %1, %2, %0;" : "+l"(a3) : "l"(xr[4 * j + 3]), "l"(w1.y));
        }
        asm("add.rn.f32x2 %0, %0, %1;" : "+l"(a0) : "l"(a1));
        asm("add.rn.f32x2 %0, %0, %1;" : "+l"(a2) : "l"(a3));
        asm("add.rn.f32x2 %0, %0, %1;" : "+l"(a0) : "l"(a2));
        float lo, hi;
        asm("mov.b64 {%0, %1}, %2;" : "=f"(lo), "=f"(hi) : "l"(a0));
        float dot = lo + hi;
        // match reference association: (xnorm + wnorm_k) - 2*dot
        float dv = (xnorm + wn[k]) - 2.0f * dot;
        if (dv < bestd) { bestd = dv; bestk = k; }  // strict <  => first-min tie rule
    }

    // indices (as f32) live after loss + quantized + perplexity
    out[1 + QELEMS + 1 + p] = (float)bestk;
    atomicAdd(&hist[bestk], 1u);

    // local loss contribution sum_d (w[bestk][d] - x[d])^2
    const float* wb = ws + bestk * DIM;
    float lsum = 0.f;
#pragma unroll
    for (int j = 0; j < 32; j++) {
        float a, b;
        asm("mov.b64 {%0, %1}, %2;" : "=f"(a), "=f"(b) : "l"(xr[j]));
        float da = wb[2 * j + 0] - a;
        float db = wb[2 * j + 1] - b;
        lsum += da * da;
        lsum += db * db;
    }
#pragma unroll
    for (int off = 16; off > 0; off >>= 1)
        lsum += __shfl_down_sync(0xffffffffu, lsum, off);
    if ((tid & 31) == 0) atomicAdd(&g_loss, (double)lsum);

    // quantized output, NCHW (coalesced across tid per channel)
    float* qout = out + 1 + n * CHW + hw;
#pragma unroll
    for (int c = 0; c < DIM; c++) qout[c * HW] = wb[c];

    __syncthreads();
    for (int i = tid; i < NUM_K; i += TILE) {
        unsigned int h = hist[i];
        if (h) atomicAdd(&g_counts[i], h);
    }
}

__global__ void vq_fin(float* __restrict__ out) {
    __shared__ float red[NUM_K];
    int k = threadIdx.x;
    float pr = (float)g_counts[k] / (float)NPOS;
    red[k] = pr * logf(pr + 1e-10f);
    __syncthreads();
    for (int s = 256; s > 0; s >>= 1) {
        if (k < s) red[k] += red[k + s];
        __syncthreads();
    }
    if (k == 0) {
        out[0] = (float)(g_loss * (1.25 / (double)QELEMS));  // q_loss + 0.25*e_loss
        out[1 + QELEMS] = expf(-red[0]);                      // perplexity
    }
}

extern "C" void kernel_launch(void* const* d_in, const int* in_sizes, int n_in,
                              void* d_out, int out_size) {
    const float* x = (const float*)d_in[0];   // [32,64,64,64] f32 NCHW
    const float* w = (const float*)d_in[1];   // [512,64] f32
    float* out = (float*)d_out;

    cudaFuncSetAttribute(vq_main, cudaFuncAttributeMaxDynamicSharedMemorySize, SMEM_BYTES);

    vq_init<<<1, NUM_K>>>(w);
    vq_main<<<NPOS / TILE, TILE, SMEM_BYTES>>>(x, w, out);
    vq_fin<<<1, NUM_K>>>(out);
}

// round 3
// speedup vs baseline: 1.5197x; 1.5197x over previous
#include <cuda_runtime.h>

#define NUM_K 512
#define DIM 64
#define HW 4096
#define CHW 262144        // 64 * 4096
#define NPOS 131072       // 32 * 64 * 64
#define QELEMS 8388608    // NPOS * DIM
#define TILE 128          // threads per CTA (one position per thread)
#define PK 128            // codes per smem phase
#define NPH (NUM_K / PK)  // 4 phases

__device__ double g_loss;
__device__ unsigned int g_counts[NUM_K];
__device__ float g_wnorm[NUM_K];

// One block per code: wnorm + zero counts/loss. Fully parallel (was 19.9us serial).
__global__ void vq_pre(const float* __restrict__ w) {
    int k = blockIdx.x;
    int d = threadIdx.x;     // 64 threads
    float v = w[k * DIM + d];
    v = v * v;
#pragma unroll
    for (int off = 16; off > 0; off >>= 1)
        v += __shfl_down_sync(0xffffffffu, v, off);
    __shared__ float s2[2];
    if ((d & 31) == 0) s2[d >> 5] = v;
    __syncthreads();
    if (d == 0) {
        g_wnorm[k] = s2[0] + s2[1];
        g_counts[k] = 0u;
        if (k == 0) g_loss = 0.0;
    }
}

__global__ __launch_bounds__(TILE, 4) void vq_main(const float* __restrict__ x,
                                                   const float* __restrict__ w,
                                                   float* __restrict__ out) {
    __shared__ float ws[PK * DIM];   // 32 KB phase tile
    __shared__ float wn[PK];

    const int tid = threadIdx.x;
    const int p  = blockIdx.x * TILE + tid;   // flattened NHW position
    const int n  = p >> 12;
    const int hw = p & 4095;
    const float* xb = x + n * CHW + hw;

    // Load this position's 64-dim vector (coalesced), pack into f32x2 regs.
    unsigned long long xr[32];
    float xnorm = 0.f;
#pragma unroll
    for (int j = 0; j < 32; j++) {
        float a = xb[(2 * j) * HW];
        float b = xb[(2 * j + 1) * HW];
        xnorm += a * a;
        xnorm += b * b;
        asm("mov.b64 %0, {%1, %2};" : "=l"(xr[j]) : "f"(a), "f"(b));
    }

    float bestd = 3.402823466e38f;
    int bestk = 0;

    for (int ph = 0; ph < NPH; ph++) {
        __syncthreads();   // protect smem reuse across phases
        // Stage 32 KB codebook phase (coalesced float4): 2048 float4 / 128 thr
        const float4* wsrc = (const float4*)(w + ph * PK * DIM);
        float4* wdst = (float4*)ws;
#pragma unroll
        for (int i = 0; i < PK * DIM / 4 / TILE; i++)
            wdst[tid + i * TILE] = wsrc[tid + i * TILE];
        if (tid < PK) wn[tid] = g_wnorm[ph * PK + tid];
        __syncthreads();

        const int kbase = ph * PK;
        for (int kk = 0; kk < PK; kk++) {
            const ulonglong2* wp = (const ulonglong2*)(ws + kk * DIM);
            unsigned long long a0 = 0ull, a1 = 0ull, a2 = 0ull, a3 = 0ull;
#pragma unroll
            for (int j = 0; j < 8; j++) {
                ulonglong2 w0 = wp[2 * j];
                ulonglong2 w1 = wp[2 * j + 1];
                asm("fma.rn.f32x2 %0, %1, %2, %0;" : "+l"(a0) : "l"(xr[4 * j + 0]), "l"(w0.x));
                asm("fma.rn.f32x2 %0, %1, %2, %0;" : "+l"(a1) : "l"(xr[4 * j + 1]), "l"(w0.y));
                asm("fma.rn.f32x2 %0, %1, %2, %0;" : "+l"(a2) : "l"(xr[4 * j + 2]), "l"(w1.x));
                asm("fma.rn.f32x2 %0, %1, %2, %0;" : "+l"(a3) : "l"(xr[4 * j + 3]), "l"(w1.y));
            }
            asm("add.rn.f32x2 %0, %0, %1;" : "+l"(a0) : "l"(a1));
            asm("add.rn.f32x2 %0, %0, %1;" : "+l"(a2) : "l"(a3));
            asm("add.rn.f32x2 %0, %0, %1;" : "+l"(a0) : "l"(a2));
            float lo, hi;
            asm("mov.b64 {%0, %1}, %2;" : "=f"(lo), "=f"(hi) : "l"(a0));
            float dot = lo + hi;
            // identical association to reference: (xnorm + wnorm_k) - 2*dot
            float dv = (xnorm + wn[kk]) - 2.0f * dot;
            if (dv < bestd) { bestd = dv; bestk = kbase + kk; }  // first-min tie rule
        }
    }

    // indices (as f32) after loss + quantized + perplexity
    out[1 + QELEMS + 1 + p] = (float)bestk;
    atomicAdd(&g_counts[bestk], 1u);

    // Winning row from global (codebook is L2/L1 hot). Two 32-float halves to cap regs.
    const float4* wg = (const float4*)(w + bestk * DIM);
    float* qout = out + 1 + n * CHW + hw;
    float lsum = 0.f;
#pragma unroll
    for (int h = 0; h < 2; h++) {
        float wv[32];
#pragma unroll
        for (int q = 0; q < 8; q++) {
            float4 r = __ldg(wg + h * 8 + q);
            wv[4 * q + 0] = r.x; wv[4 * q + 1] = r.y;
            wv[4 * q + 2] = r.z; wv[4 * q + 3] = r.w;
        }
#pragma unroll
        for (int j = 0; j < 16; j++) {
            float a, b;
            asm("mov.b64 {%0, %1}, %2;" : "=f"(a), "=f"(b) : "l"(xr[h * 16 + j]));
            float da = wv[2 * j + 0] - a;
            float db = wv[2 * j + 1] - b;
            lsum += da * da;
            lsum += db * db;
        }
#pragma unroll
        for (int c = 0; c < 32; c++) qout[(h * 32 + c) * HW] = wv[c];
    }

#pragma unroll
    for (int off = 16; off > 0; off >>= 1)
        lsum += __shfl_down_sync(0xffffffffu, lsum, off);
    if ((tid & 31) == 0) atomicAdd(&g_loss, (double)lsum);
}

__global__ void vq_fin(float* __restrict__ out) {
    __shared__ float red[NUM_K];
    int k = threadIdx.x;
    float pr = (float)g_counts[k] / (float)NPOS;
    red[k] = pr * logf(pr + 1e-10f);
    __syncthreads();
    for (int s = 256; s > 0; s >>= 1) {
        if (k < s) red[k] += red[k + s];
        __syncthreads();
    }
    if (k == 0) {
        out[0] = (float)(g_loss * (1.25 / (double)QELEMS));  // q_loss + 0.25*e_loss
        out[1 + QELEMS] = expf(-red[0]);                      // perplexity
    }
}

extern "C" void kernel_launch(void* const* d_in, const int* in_sizes, int n_in,
                              void* d_out, int out_size) {
    const float* x = (const float*)d_in[0];   // [32,64,64,64] f32 NCHW
    const float* w = (const float*)d_in[1];   // [512,64] f32
    float* out = (float*)d_out;

    vq_pre<<<NUM_K, 64>>>(w);
    vq_main<<<NPOS / TILE, TILE>>>(x, w, out);
    vq_fin<<<1, NUM_K>>>(out);
}